// round 9
// baseline (speedup 1.0000x reference)
#include <cuda_runtime.h>
#include <cstdint>

// ---------------------------------------------------------------------------
// GraphSAGE 2-layer, N=100000, E=1.6M, 128 -> 128(relu) -> 64, fp32.
//
//  * edge_index is INT32 (JAX x64 disabled => jnp.int64 silently -> int32).
//    Reading it as int64 was the cause of all prior traps (717/700).
//  * Inputs identified BY SIZE (robust to metadata ordering):
//      x: 12,800,000  edge_index: 3,200,000 (int32)
//      W1_l/W1_r: 16,384 (first = _l)  W2_l/W2_r: 8,192  b1: 128  b2: 64
//  * Node indices clamped in CSR build (insurance only).
//  * mean-agg linear => GEMM-before-aggregate; CSR + warp-per-node gather.
//  * Static smem only; kernel_launch = kernel launches only.
// ---------------------------------------------------------------------------

#define MAX_N 100000
#define MAX_E 1600000
#define SCAN_BLK 1024
#define MAX_SCAN_BLKS ((MAX_N + SCAN_BLK - 1) / SCAN_BLK)   // 98

__device__ int g_cnt[MAX_N];          // in-degree histogram
__device__ int g_cursor[MAX_N];       // fill cursors
__device__ int g_rowptr[MAX_N + 1];   // CSR row pointers
__device__ int g_bsum[MAX_SCAN_BLKS]; // scan block sums
__device__ int g_esrc[MAX_E];         // CSR: src node per incoming edge

// float4-typed for guaranteed 16B alignment
__device__ float4 g_y1[(size_t)MAX_N * 32];  // x @ W1_l   [N,128]
__device__ float4 g_r1[(size_t)MAX_N * 32];  // x @ W1_r   [N,128]
__device__ float4 g_h [(size_t)MAX_N * 32];  // hidden     [N,128]
__device__ float4 g_y2[(size_t)MAX_N * 16];  // h @ W2_l   [N,64]
__device__ float4 g_r2[(size_t)MAX_N * 16];  // h @ W2_r   [N,64]

__device__ __forceinline__ int clampi(int v, int lo, int hi) {
    return v < lo ? lo : (v > hi ? hi : v);
}

// ---------------------------- CSR build -------------------------------------
__global__ void zero_kernel(int N) {
    for (int i = blockIdx.x * blockDim.x + threadIdx.x;
         i < N; i += gridDim.x * blockDim.x) {
        g_cnt[i] = 0;
        g_cursor[i] = 0;
    }
}

__global__ void count_kernel(const int* __restrict__ dst, int E, int N) {
    int i = blockIdx.x * blockDim.x + threadIdx.x;
    if (i < E) {
        int d = clampi(dst[i], 0, N - 1);
        atomicAdd(&g_cnt[d], 1);
    }
}

// Phase 1: per-block exclusive scan of g_cnt (block = 1024 elems)
__global__ void scan1_kernel(int N) {
    __shared__ int sm[SCAN_BLK];
    int i = blockIdx.x * SCAN_BLK + threadIdx.x;
    int v = (i < N) ? g_cnt[i] : 0;
    sm[threadIdx.x] = v;
    __syncthreads();
    #pragma unroll
    for (int off = 1; off < SCAN_BLK; off <<= 1) {
        int t = (threadIdx.x >= off) ? sm[threadIdx.x - off] : 0;
        __syncthreads();
        sm[threadIdx.x] += t;
        __syncthreads();
    }
    int incl = sm[threadIdx.x];
    if (i < N) g_rowptr[i] = incl - v;                 // exclusive
    if (threadIdx.x == SCAN_BLK - 1) g_bsum[blockIdx.x] = incl;
}

// Phase 2: serial exclusive scan of the (<=98) block sums
__global__ void scan2_kernel(int nblk) {
    if (threadIdx.x == 0 && blockIdx.x == 0) {
        int run = 0;
        for (int b = 0; b < nblk; ++b) {
            int t = g_bsum[b];
            g_bsum[b] = run;
            run += t;
        }
    }
}

// Phase 3: add block offsets; set rowptr[N] = E
__global__ void scan3_kernel(int N, int E) {
    int i = blockIdx.x * blockDim.x + threadIdx.x;
    if (i < N) g_rowptr[i] += g_bsum[i / SCAN_BLK];
    if (i == 0) g_rowptr[N] = E;
}

__global__ void fill_kernel(const int* __restrict__ src,
                            const int* __restrict__ dst, int E, int N) {
    int i = blockIdx.x * blockDim.x + threadIdx.x;
    if (i >= E) return;
    int d = clampi(dst[i], 0, N - 1);
    int s = clampi(src[i], 0, N - 1);
    int pos = atomicAdd(&g_cursor[d], 1);
    int at  = g_rowptr[d] + pos;
    if (at >= 0 && at < E) g_esrc[at] = s;
}

// ---------------------------- fp32 GEMM, K=128 ------------------------------
// C = out cols (128/64). 256 threads, 64-row x C-col tile.
// A tile [64][132] in STATIC smem (33.8 KB). W via __ldg (L1-resident).
// Thread (ty,tx) computes 4 rows x (C/16) cols.
// SRC_H: read A from g_h. DST: 0=g_y1 1=g_r1 2=g_y2 3=g_r2.
template <int C, bool SRC_H, int DST>
__global__ void __launch_bounds__(256)
gemm_k128(const float* __restrict__ Ain, const float* __restrict__ W, int N) {
    constexpr int TN = C / 16;           // 8 or 4
    __shared__ float As[64 * 132];

    const float* A = SRC_H ? reinterpret_cast<const float*>(g_h) : Ain;
    float* out =
        DST == 0 ? reinterpret_cast<float*>(g_y1) :
        DST == 1 ? reinterpret_cast<float*>(g_r1) :
        DST == 2 ? reinterpret_cast<float*>(g_y2) :
                   reinterpret_cast<float*>(g_r2);

    const int tid  = threadIdx.x;
    const int row0 = blockIdx.x * 64;

    const float4* A4 = reinterpret_cast<const float4*>(A);
    #pragma unroll
    for (int idx = tid; idx < 64 * 32; idx += 256) {
        int r = idx >> 5, k4 = idx & 31;
        float4 v = make_float4(0.f, 0.f, 0.f, 0.f);
        if (row0 + r < N) v = A4[(size_t)(row0 + r) * 32 + k4];
        *reinterpret_cast<float4*>(&As[r * 132 + k4 * 4]) = v;
    }
    __syncthreads();

    const int tx = tid & 15;             // col group (16)
    const int ty = tid >> 4;             // row group (16), 4 rows each

    float acc[4][TN];
    #pragma unroll
    for (int i = 0; i < 4; ++i)
        #pragma unroll
        for (int j = 0; j < TN; ++j) acc[i][j] = 0.f;

    const float4* Wv = reinterpret_cast<const float4*>(W);

    #pragma unroll 4
    for (int k = 0; k < 128; ++k) {
        float a[4];
        #pragma unroll
        for (int i = 0; i < 4; ++i) a[i] = As[(ty * 4 + i) * 132 + k];
        float b[TN];
        #pragma unroll
        for (int j = 0; j < TN; j += 4) {
            float4 bv = __ldg(&Wv[(k * C + tx * TN + j) >> 2]);
            b[j] = bv.x; b[j + 1] = bv.y; b[j + 2] = bv.z; b[j + 3] = bv.w;
        }
        #pragma unroll
        for (int i = 0; i < 4; ++i)
            #pragma unroll
            for (int j = 0; j < TN; ++j)
                acc[i][j] = fmaf(a[i], b[j], acc[i][j]);
    }

    #pragma unroll
    for (int i = 0; i < 4; ++i) {
        int r = row0 + ty * 4 + i;
        if (r < N) {
            #pragma unroll
            for (int j = 0; j < TN; j += 4) {
                float4 v = make_float4(acc[i][j], acc[i][j + 1],
                                       acc[i][j + 2], acc[i][j + 3]);
                *reinterpret_cast<float4*>(&out[(size_t)r * C + tx * TN + j]) = v;
            }
        }
    }
}

// ------------------- gather + combine (layer 1, d=128) -----------------------
// Warp per node; lane = float4 chunk. h = relu(mean(y1[src]) + b1 + r1).
__global__ void gather_combine1(const float* __restrict__ b1, int N) {
    int warp = (blockIdx.x * blockDim.x + threadIdx.x) >> 5;
    int lane = threadIdx.x & 31;
    if (warp >= N) return;
    int beg = g_rowptr[warp], end = g_rowptr[warp + 1];
    float4 acc = make_float4(0.f, 0.f, 0.f, 0.f);
    int s_next = (beg < end) ? g_esrc[beg] : 0;
    for (int i = beg; i < end; ++i) {
        int s = s_next;
        if (i + 1 < end) s_next = g_esrc[i + 1];
        float4 v = g_y1[(size_t)s * 32 + lane];
        acc.x += v.x; acc.y += v.y; acc.z += v.z; acc.w += v.w;
    }
    float inv = 1.0f / fmaxf((float)(end - beg), 1.0f);
    float4 r = g_r1[(size_t)warp * 32 + lane];
    float4 bb = reinterpret_cast<const float4*>(b1)[lane];
    float4 o;
    o.x = fmaxf(fmaf(acc.x, inv, bb.x + r.x), 0.f);
    o.y = fmaxf(fmaf(acc.y, inv, bb.y + r.y), 0.f);
    o.z = fmaxf(fmaf(acc.z, inv, bb.z + r.z), 0.f);
    o.w = fmaxf(fmaf(acc.w, inv, bb.w + r.w), 0.f);
    g_h[(size_t)warp * 32 + lane] = o;
}

// ------------------- gather + combine (layer 2, d=64) ------------------------
// Warp per node; lane = float2 chunk. out = mean(y2[src]) + b2 + r2.
__global__ void gather_combine2(const float* __restrict__ b2,
                                float* __restrict__ out, int N) {
    int warp = (blockIdx.x * blockDim.x + threadIdx.x) >> 5;
    int lane = threadIdx.x & 31;
    if (warp >= N) return;
    int beg = g_rowptr[warp], end = g_rowptr[warp + 1];
    const float2* y2 = reinterpret_cast<const float2*>(g_y2);
    float2 acc = make_float2(0.f, 0.f);
    int s_next = (beg < end) ? g_esrc[beg] : 0;
    for (int i = beg; i < end; ++i) {
        int s = s_next;
        if (i + 1 < end) s_next = g_esrc[i + 1];
        float2 v = y2[(size_t)s * 32 + lane];
        acc.x += v.x; acc.y += v.y;
    }
    float inv = 1.0f / fmaxf((float)(end - beg), 1.0f);
    float2 r = reinterpret_cast<const float2*>(g_r2)[(size_t)warp * 32 + lane];
    float2 bb = reinterpret_cast<const float2*>(b2)[lane];
    float2 o;
    o.x = fmaf(acc.x, inv, bb.x + r.x);
    o.y = fmaf(acc.y, inv, bb.y + r.y);
    reinterpret_cast<float2*>(out)[(size_t)warp * 32 + lane] = o;
}

// ---------------------------- launch ----------------------------------------
extern "C" void kernel_launch(void* const* d_in, const int* in_sizes, int n_in,
                              void* d_out, int out_size) {
    // --- identify inputs by element count (robust to metadata ordering) ---
    const float* x = nullptr;
    const int*   ei = nullptr;     // edge_index is int32 (JAX x64 disabled)
    const float *W1_l = nullptr, *W1_r = nullptr;
    const float *W2_l = nullptr, *W2_r = nullptr;
    const float *b1 = nullptr, *b2 = nullptr;

    for (int i = 0; i < n_in; ++i) {
        int sz = in_sizes[i];
        void* p = d_in[i];
        if      (sz == 12800000) x = (const float*)p;          // N*128
        else if (sz == 3200000)  ei = (const int*)p;           // 2*E int32
        else if (sz == 16384)  { if (!W1_l) W1_l = (const float*)p;
                                 else       W1_r = (const float*)p; }
        else if (sz == 8192)   { if (!W2_l) W2_l = (const float*)p;
                                 else       W2_r = (const float*)p; }
        else if (sz == 128)      b1 = (const float*)p;
        else if (sz == 64)       b2 = (const float*)p;
    }
    if (!x || !ei || !W1_l || !W1_r || !W2_l || !W2_r || !b1 || !b2) return;

    const int N = 12800000 / 128;      // 100000
    const int E = 3200000 / 2;         // 1600000
    const int* src = ei;               // edge_index row 0
    const int* dst = ei + E;           // edge_index row 1

    // ---- CSR build ----
    zero_kernel<<<128, 256>>>(N);
    count_kernel<<<(E + 255) / 256, 256>>>(dst, E, N);
    int nblk = (N + SCAN_BLK - 1) / SCAN_BLK;
    scan1_kernel<<<nblk, SCAN_BLK>>>(N);
    scan2_kernel<<<1, 32>>>(nblk);
    scan3_kernel<<<(N + 255) / 256, 256>>>(N, E);
    fill_kernel<<<(E + 255) / 256, 256>>>(src, dst, E, N);

    const int gblocks = (N + 63) / 64;
    const int wblocks = (N * 32 + 255) / 256;   // warp-per-node, 8 warps/block

    // ---- layer 1 ----
    gemm_k128<128, false, 0><<<gblocks, 256>>>(x, W1_l, N);
    gemm_k128<128, false, 1><<<gblocks, 256>>>(x, W1_r, N);
    gather_combine1<<<wblocks, 256>>>(b1, N);

    // ---- layer 2 ----
    gemm_k128<64, true, 2><<<gblocks, 256>>>(nullptr, W2_l, N);
    gemm_k128<64, true, 3><<<gblocks, 256>>>(nullptr, W2_r, N);
    gather_combine2<<<wblocks, 256>>>(b2, (float*)d_out, N);
}

// round 10
// speedup vs baseline: 1.1631x; 1.1631x over previous
#include <cuda_runtime.h>
#include <cstdint>

// ---------------------------------------------------------------------------
// GraphSAGE 2-layer, N=100000, E=1.6M, 128 -> 128(relu) -> 64, fp32.
//
// R9 passed (600 us). R10 changes:
//  * GEMM inner loop uses fma.rn.f32x2 (packed dual fp32 FMA, sm_100+):
//    halves fma-pipe issue count at identical fp32 precision.
//  * Per-layer GEMM pairs fused into one kernel (shared A tile, both W's).
// Everything else (int32 edge_index, size-based input ID, CSR + warp-gather,
// static smem only, launches-only capture) unchanged from the passing R9.
// ---------------------------------------------------------------------------

#define MAX_N 100000
#define MAX_E 1600000
#define SCAN_BLK 1024
#define MAX_SCAN_BLKS ((MAX_N + SCAN_BLK - 1) / SCAN_BLK)   // 98

__device__ int g_cnt[MAX_N];
__device__ int g_cursor[MAX_N];
__device__ int g_rowptr[MAX_N + 1];
__device__ int g_bsum[MAX_SCAN_BLKS];
__device__ int g_esrc[MAX_E];

__device__ float4 g_y1[(size_t)MAX_N * 32];  // x @ W1_l   [N,128]
__device__ float4 g_r1[(size_t)MAX_N * 32];  // x @ W1_r   [N,128]
__device__ float4 g_h [(size_t)MAX_N * 32];  // hidden     [N,128]
__device__ float4 g_y2[(size_t)MAX_N * 16];  // h @ W2_l   [N,64]
__device__ float4 g_r2[(size_t)MAX_N * 16];  // h @ W2_r   [N,64]

__device__ __forceinline__ int clampi(int v, int lo, int hi) {
    return v < lo ? lo : (v > hi ? hi : v);
}

// ---------------- packed f32x2 helpers (sm_100+) -----------------------------
__device__ __forceinline__ uint64_t pack2(float lo, float hi) {
    uint64_t r;
    asm("mov.b64 %0, {%1, %2};" : "=l"(r) : "f"(lo), "f"(hi));
    return r;
}
__device__ __forceinline__ void unpack2(uint64_t v, float& lo, float& hi) {
    asm("mov.b64 {%0, %1}, %2;" : "=f"(lo), "=f"(hi) : "l"(v));
}
__device__ __forceinline__ void fma2(uint64_t& d, uint64_t a, uint64_t b) {
    asm("fma.rn.f32x2 %0, %1, %2, %3;" : "=l"(d) : "l"(a), "l"(b), "l"(d));
}

// ---------------------------- CSR build -------------------------------------
__global__ void zero_kernel(int N) {
    for (int i = blockIdx.x * blockDim.x + threadIdx.x;
         i < N; i += gridDim.x * blockDim.x) {
        g_cnt[i] = 0;
        g_cursor[i] = 0;
    }
}

__global__ void count_kernel(const int* __restrict__ dst, int E, int N) {
    int i = blockIdx.x * blockDim.x + threadIdx.x;
    if (i < E) {
        int d = clampi(dst[i], 0, N - 1);
        atomicAdd(&g_cnt[d], 1);
    }
}

__global__ void scan1_kernel(int N) {
    __shared__ int sm[SCAN_BLK];
    int i = blockIdx.x * SCAN_BLK + threadIdx.x;
    int v = (i < N) ? g_cnt[i] : 0;
    sm[threadIdx.x] = v;
    __syncthreads();
    #pragma unroll
    for (int off = 1; off < SCAN_BLK; off <<= 1) {
        int t = (threadIdx.x >= off) ? sm[threadIdx.x - off] : 0;
        __syncthreads();
        sm[threadIdx.x] += t;
        __syncthreads();
    }
    int incl = sm[threadIdx.x];
    if (i < N) g_rowptr[i] = incl - v;
    if (threadIdx.x == SCAN_BLK - 1) g_bsum[blockIdx.x] = incl;
}

__global__ void scan2_kernel(int nblk) {
    if (threadIdx.x == 0 && blockIdx.x == 0) {
        int run = 0;
        for (int b = 0; b < nblk; ++b) {
            int t = g_bsum[b];
            g_bsum[b] = run;
            run += t;
        }
    }
}

__global__ void scan3_kernel(int N, int E) {
    int i = blockIdx.x * blockDim.x + threadIdx.x;
    if (i < N) g_rowptr[i] += g_bsum[i / SCAN_BLK];
    if (i == 0) g_rowptr[N] = E;
}

__global__ void fill_kernel(const int* __restrict__ src,
                            const int* __restrict__ dst, int E, int N) {
    int i = blockIdx.x * blockDim.x + threadIdx.x;
    if (i >= E) return;
    int d = clampi(dst[i], 0, N - 1);
    int s = clampi(src[i], 0, N - 1);
    int pos = atomicAdd(&g_cursor[d], 1);
    int at  = g_rowptr[d] + pos;
    if (at >= 0 && at < E) g_esrc[at] = s;
}

// ------------------- fused dual GEMM, K=128, packed f32x2 --------------------
// Computes A@Wl and A@Wr in one pass (shared A tile).
// C = cols per matrix (128 layer1 / 64 layer2). 256 threads, 64-row tile.
// A tile [64][132] static smem; W via __ldg (L1-resident, <=128 KB total).
// Thread (ty,tx): 4 rows x TN cols per matrix, accumulators packed f32x2.
// LAYER==1: A=Ain(x) -> g_y1,g_r1.  LAYER==2: A=g_h -> g_y2,g_r2.
template <int C, int LAYER>
__global__ void __launch_bounds__(256)
gemm_fused(const float* __restrict__ Ain, const float* __restrict__ Wl,
           const float* __restrict__ Wr, int N) {
    constexpr int TN = C / 16;           // cols/thread/matrix: 8 or 4
    constexpr int TP = TN / 2;           // packed accs/row/matrix: 4 or 2
    __shared__ float As[64 * 132];

    const float* A = (LAYER == 1) ? Ain : reinterpret_cast<const float*>(g_h);
    float* out_l = (LAYER == 1) ? reinterpret_cast<float*>(g_y1)
                                : reinterpret_cast<float*>(g_y2);
    float* out_r = (LAYER == 1) ? reinterpret_cast<float*>(g_r1)
                                : reinterpret_cast<float*>(g_r2);

    const int tid  = threadIdx.x;
    const int row0 = blockIdx.x * 64;

    // A tile: coalesced float4 loads, padded stride 132 -> conflict-free
    const float4* A4 = reinterpret_cast<const float4*>(A);
    #pragma unroll
    for (int idx = tid; idx < 64 * 32; idx += 256) {
        int r = idx >> 5, k4 = idx & 31;
        float4 v = make_float4(0.f, 0.f, 0.f, 0.f);
        if (row0 + r < N) v = A4[(size_t)(row0 + r) * 32 + k4];
        *reinterpret_cast<float4*>(&As[r * 132 + k4 * 4]) = v;
    }
    __syncthreads();

    const int tx = tid & 15;             // col group (16 x TN = C)
    const int ty = tid >> 4;             // row group (16 x 4 = 64)

    uint64_t accl[4][TP], accr[4][TP];
    #pragma unroll
    for (int i = 0; i < 4; ++i)
        #pragma unroll
        for (int j = 0; j < TP; ++j) { accl[i][j] = 0ull; accr[i][j] = 0ull; }

    const float4* Wl4 = reinterpret_cast<const float4*>(Wl);
    const float4* Wr4 = reinterpret_cast<const float4*>(Wr);

    #pragma unroll 4
    for (int k = 0; k < 128; ++k) {
        uint64_t aa[4];
        #pragma unroll
        for (int i = 0; i < 4; ++i) {
            float a = As[(ty * 4 + i) * 132 + k];
            aa[i] = pack2(a, a);
        }
        uint64_t bl[TP], br[TP];
        #pragma unroll
        for (int j = 0; j < TP; j += 2) {     // one float4 = two packed pairs
            float4 v = __ldg(&Wl4[(k * C + tx * TN + j * 2) >> 2]);
            bl[j]     = pack2(v.x, v.y);
            bl[j + 1] = pack2(v.z, v.w);
            float4 w = __ldg(&Wr4[(k * C + tx * TN + j * 2) >> 2]);
            br[j]     = pack2(w.x, w.y);
            br[j + 1] = pack2(w.z, w.w);
        }
        #pragma unroll
        for (int i = 0; i < 4; ++i) {
            #pragma unroll
            for (int j = 0; j < TP; ++j) {
                fma2(accl[i][j], aa[i], bl[j]);
                fma2(accr[i][j], aa[i], br[j]);
            }
        }
    }

    #pragma unroll
    for (int i = 0; i < 4; ++i) {
        int r = row0 + ty * 4 + i;
        if (r < N) {
            #pragma unroll
            for (int j = 0; j < TP; j += 2) {
                float4 v;
                unpack2(accl[i][j],     v.x, v.y);
                unpack2(accl[i][j + 1], v.z, v.w);
                *reinterpret_cast<float4*>(
                    &out_l[(size_t)r * C + tx * TN + j * 2]) = v;
                float4 w;
                unpack2(accr[i][j],     w.x, w.y);
                unpack2(accr[i][j + 1], w.z, w.w);
                *reinterpret_cast<float4*>(
                    &out_r[(size_t)r * C + tx * TN + j * 2]) = w;
            }
        }
    }
}

// ------------------- gather + combine (layer 1, d=128) -----------------------
__global__ void gather_combine1(const float* __restrict__ b1, int N) {
    int warp = (blockIdx.x * blockDim.x + threadIdx.x) >> 5;
    int lane = threadIdx.x & 31;
    if (warp >= N) return;
    int beg = g_rowptr[warp], end = g_rowptr[warp + 1];
    float4 acc = make_float4(0.f, 0.f, 0.f, 0.f);
    int s_next = (beg < end) ? g_esrc[beg] : 0;
    for (int i = beg; i < end; ++i) {
        int s = s_next;
        if (i + 1 < end) s_next = g_esrc[i + 1];
        float4 v = g_y1[(size_t)s * 32 + lane];
        acc.x += v.x; acc.y += v.y; acc.z += v.z; acc.w += v.w;
    }
    float inv = 1.0f / fmaxf((float)(end - beg), 1.0f);
    float4 r = g_r1[(size_t)warp * 32 + lane];
    float4 bb = reinterpret_cast<const float4*>(b1)[lane];
    float4 o;
    o.x = fmaxf(fmaf(acc.x, inv, bb.x + r.x), 0.f);
    o.y = fmaxf(fmaf(acc.y, inv, bb.y + r.y), 0.f);
    o.z = fmaxf(fmaf(acc.z, inv, bb.z + r.z), 0.f);
    o.w = fmaxf(fmaf(acc.w, inv, bb.w + r.w), 0.f);
    g_h[(size_t)warp * 32 + lane] = o;
}

// ------------------- gather + combine (layer 2, d=64) ------------------------
__global__ void gather_combine2(const float* __restrict__ b2,
                                float* __restrict__ out, int N) {
    int warp = (blockIdx.x * blockDim.x + threadIdx.x) >> 5;
    int lane = threadIdx.x & 31;
    if (warp >= N) return;
    int beg = g_rowptr[warp], end = g_rowptr[warp + 1];
    const float2* y2 = reinterpret_cast<const float2*>(g_y2);
    float2 acc = make_float2(0.f, 0.f);
    int s_next = (beg < end) ? g_esrc[beg] : 0;
    for (int i = beg; i < end; ++i) {
        int s = s_next;
        if (i + 1 < end) s_next = g_esrc[i + 1];
        float2 v = y2[(size_t)s * 32 + lane];
        acc.x += v.x; acc.y += v.y;
    }
    float inv = 1.0f / fmaxf((float)(end - beg), 1.0f);
    float2 r = reinterpret_cast<const float2*>(g_r2)[(size_t)warp * 32 + lane];
    float2 bb = reinterpret_cast<const float2*>(b2)[lane];
    float2 o;
    o.x = fmaf(acc.x, inv, bb.x + r.x);
    o.y = fmaf(acc.y, inv, bb.y + r.y);
    reinterpret_cast<float2*>(out)[(size_t)warp * 32 + lane] = o;
}

// ---------------------------- launch ----------------------------------------
extern "C" void kernel_launch(void* const* d_in, const int* in_sizes, int n_in,
                              void* d_out, int out_size) {
    // --- identify inputs by element count (robust to metadata ordering) ---
    const float* x = nullptr;
    const int*   ei = nullptr;     // edge_index is int32 (JAX x64 disabled)
    const float *W1_l = nullptr, *W1_r = nullptr;
    const float *W2_l = nullptr, *W2_r = nullptr;
    const float *b1 = nullptr, *b2 = nullptr;

    for (int i = 0; i < n_in; ++i) {
        int sz = in_sizes[i];
        void* p = d_in[i];
        if      (sz == 12800000) x = (const float*)p;          // N*128
        else if (sz == 3200000)  ei = (const int*)p;           // 2*E int32
        else if (sz == 16384)  { if (!W1_l) W1_l = (const float*)p;
                                 else       W1_r = (const float*)p; }
        else if (sz == 8192)   { if (!W2_l) W2_l = (const float*)p;
                                 else       W2_r = (const float*)p; }
        else if (sz == 128)      b1 = (const float*)p;
        else if (sz == 64)       b2 = (const float*)p;
    }
    if (!x || !ei || !W1_l || !W1_r || !W2_l || !W2_r || !b1 || !b2) return;

    const int N = 12800000 / 128;      // 100000
    const int E = 3200000 / 2;         // 1600000
    const int* src = ei;               // edge_index row 0
    const int* dst = ei + E;           // edge_index row 1

    // ---- CSR build ----
    zero_kernel<<<128, 256>>>(N);
    count_kernel<<<(E + 255) / 256, 256>>>(dst, E, N);
    int nblk = (N + SCAN_BLK - 1) / SCAN_BLK;
    scan1_kernel<<<nblk, SCAN_BLK>>>(N);
    scan2_kernel<<<1, 32>>>(nblk);
    scan3_kernel<<<(N + 255) / 256, 256>>>(N, E);
    fill_kernel<<<(E + 255) / 256, 256>>>(src, dst, E, N);

    const int gblocks = (N + 63) / 64;
    const int wblocks = (N * 32 + 255) / 256;   // warp-per-node, 8 warps/block

    // ---- layer 1 ----
    gemm_fused<128, 1><<<gblocks, 256>>>(x, W1_l, W1_r, N);
    gather_combine1<<<wblocks, 256>>>(b1, N);

    // ---- layer 2 ----
    gemm_fused<64, 2><<<gblocks, 256>>>(nullptr, W2_l, W2_r, N);
    gather_combine2<<<wblocks, 256>>>(b2, (float*)d_out, N);
}